// round 13
// baseline (speedup 1.0000x reference)
#include <cuda_runtime.h>
#include <cuda_bf16.h>
#include <cstdint>

#define BB   4
#define CIN  32
#define HH   320
#define WW   640
#define HWC  (HH*WW)
#define NPIX (BB*HWC)
#define CCAT 128
#define SFC  32

// ---------------- device scratch ----------------
__device__ float g_xn[(size_t)NPIX * CIN];                          // planar normalized x
__device__ float g_a[(size_t)NPIX * 32];                            // planar clamped affinities [q][pix]
__device__ __align__(256) unsigned int g_fbf[(size_t)NPIX * CCAT];  // [chunk4][pix][32 u32: hi16|lo16]
__device__ float g_h[(size_t)NPIX * SFC];                           // planar pre-BN
__device__ __align__(128) unsigned int g_wm[36864];                 // mma-fragment-ordered weights
__device__ float g_stats[512];  // [di*72 + j*8+k]=M, [di*72+64+k]=mean-sums; [352..384) h sum; [384..416) h sumsq
__device__ float g_bn[512];     // [0..128) sc feats, [128..256) sh feats, [256..288) sc h, [288..320) sh h

__device__ __forceinline__ uint32_t smem_u32(const void* p) {
    uint32_t a;
    asm("{ .reg .u64 t; cvta.to.shared.u64 t, %1; cvt.u32.u64 %0, t; }" : "=r"(a) : "l"(p));
    return a;
}
#define MMA16816(c, a, b0v, b1v) \
    asm volatile("mma.sync.aligned.m16n8k16.row.col.f32.bf16.bf16.f32 " \
                 "{%0,%1,%2,%3},{%4,%5,%6,%7},{%8,%9},{%0,%1,%2,%3};" \
                 : "+f"((c)[0]), "+f"((c)[1]), "+f"((c)[2]), "+f"((c)[3]) \
                 : "r"((a)[0]), "r"((a)[1]), "r"((a)[2]), "r"((a)[3]), "r"(b0v), "r"(b1v))

__global__ void k_zero() { g_stats[threadIdx.x] = 0.f; }

__global__ void k_norm(const float* __restrict__ x) {
    int idx = blockIdx.x * 256 + threadIdx.x;
    int b = idx / HWC, p = idx - b * HWC;
    const float* xp = x + (size_t)b * CIN * HWC + p;
    float* op = g_xn + (size_t)b * CIN * HWC + p;
    float v[CIN]; float ss = 0.f;
#pragma unroll
    for (int c = 0; c < CIN; c++) { v[c] = xp[(size_t)c * HWC]; ss += v[c] * v[c]; }
    float rn = 1.f / fmaxf(sqrtf(ss), 1e-12f);
#pragma unroll
    for (int c = 0; c < CIN; c++) op[(size_t)c * HWC] = v[c] * rn;
}

__global__ void k_aff() {
    int idx = blockIdx.x * 256 + threadIdx.x;
    int b = idx / HWC, p = idx - b * HWC;
    int y = p / WW, xx = p - y * WW;
    const float* xb = g_xn + (size_t)b * CIN * HWC;
    float cv[CIN];
#pragma unroll
    for (int c = 0; c < CIN; c++) cv[c] = xb[(size_t)c * HWC + p];
    float a[32];
#pragma unroll 1
    for (int di = 0; di < 4; di++) {
        int d = 1 << di;
        int kk = 0;
#pragma unroll
        for (int iy = -1; iy <= 1; iy++)
#pragma unroll
            for (int jx = -1; jx <= 1; jx++) {
                if (iy == 0 && jx == 0) continue;
                int ny = y + iy * d, nx = xx + jx * d;
                float dot = 0.f;
                if ((unsigned)ny < HH && (unsigned)nx < WW) {
                    int np = ny * WW + nx;
#pragma unroll
                    for (int c = 0; c < CIN; c++) dot += cv[c] * xb[(size_t)c * HWC + np];
                }
                a[di * 8 + kk] = fmaxf(dot, 0.f);
                kk++;
            }
    }
#pragma unroll
    for (int n = 0; n < 32; n++) g_a[(size_t)n * NPIX + idx] = a[n];
}

// affinity moments per branch: Sum a_j, Sum a_j*a_k (full 8x8). 800 CTAs.
__global__ void __launch_bounds__(256) k_mom() {
    int di = blockIdx.x;          // branch
    int slice = blockIdx.y;       // 200 slices of 4096 px
    int tid = threadIdx.x;
    int lane = tid & 31;
    float m[8];
    float M[8][8];
#pragma unroll
    for (int j = 0; j < 8; j++) {
        m[j] = 0.f;
#pragma unroll
        for (int k = 0; k < 8; k++) M[j][k] = 0.f;
    }
    int e0 = slice * 4096;
    for (int e = e0 + tid; e < e0 + 4096; e += 256) {
        float av[8];
#pragma unroll
        for (int k = 0; k < 8; k++) av[k] = g_a[(size_t)(di * 8 + k) * NPIX + e];
#pragma unroll
        for (int j = 0; j < 8; j++) {
            m[j] += av[j];
#pragma unroll
            for (int k = 0; k < 8; k++) M[j][k] = fmaf(av[j], av[k], M[j][k]);
        }
    }
#pragma unroll
    for (int j = 0; j < 8; j++) {
        float v = m[j];
#pragma unroll
        for (int off = 16; off > 0; off >>= 1) v += __shfl_xor_sync(0xffffffffu, v, off);
        if (lane == 0) atomicAdd(&g_stats[di * 72 + 64 + j], v);
#pragma unroll
        for (int k = 0; k < 8; k++) {
            float w = M[j][k];
#pragma unroll
            for (int off = 16; off > 0; off >>= 1) w += __shfl_xor_sync(0xffffffffu, w, off);
            if (lane == 0) atomicAdd(&g_stats[di * 72 + j * 8 + k], w);
        }
    }
}

__global__ void k_bnfin128(const float* __restrict__ w1, const float* __restrict__ w2,
                           const float* __restrict__ w3, const float* __restrict__ w4,
                           const float* __restrict__ g1, const float* __restrict__ b1,
                           const float* __restrict__ g2, const float* __restrict__ b2,
                           const float* __restrict__ g3, const float* __restrict__ b3,
                           const float* __restrict__ g4, const float* __restrict__ b4) {
    int c = threadIdx.x;
    int di = c >> 5, o = c & 31;
    const float* ws[4] = {w1, w2, w3, w4};
    const float* gs[4] = {g1, g2, g3, g4};
    const float* bs[4] = {b1, b2, b3, b4};
    float inv = 1.0f / (float)NPIX;
    const float* w = ws[di] + o * 8;
    const float* st = &g_stats[di * 72];
    float mean = 0.f;
#pragma unroll
    for (int k = 0; k < 8; k++) mean = fmaf(w[k], st[64 + k] * inv, mean);
    float ehh = 0.f;
#pragma unroll
    for (int j = 0; j < 8; j++) {
        float rj = 0.f;
#pragma unroll
        for (int k = 0; k < 8; k++) rj = fmaf(w[k], st[j * 8 + k], rj);
        ehh = fmaf(w[j], rj, ehh);
    }
    ehh *= inv;
    float var = ehh - mean * mean;
    float sc = gs[di][o] * rsqrtf(fmaxf(var, 0.f) + 1e-5f);
    g_bn[c] = sc;
    g_bn[128 + c] = bs[di][o] - mean * sc;
}

__global__ void k_stats(int which, int nch, int statoff) {
    const float* buf = which ? g_h : g_a;
    int c = blockIdx.x, slice = blockIdx.y, tid = threadIdx.x;
    const int P4 = HWC / 4;
    float s = 0.f, q = 0.f;
    int e0 = slice * 8192;
    for (int e = e0 + tid; e < e0 + 8192; e += 256) {
        int b = e / P4, p4 = e - b * P4;
        const float4* plane = reinterpret_cast<const float4*>(buf + ((size_t)b * nch + c) * HWC);
        float4 v = plane[p4];
        s += v.x + v.y + v.z + v.w;
        q += v.x * v.x + v.y * v.y + v.z * v.z + v.w * v.w;
    }
    __shared__ float ss[256], sq[256];
    ss[tid] = s; sq[tid] = q;
    __syncthreads();
    for (int off = 128; off > 0; off >>= 1) {
        if (tid < off) { ss[tid] += ss[tid + off]; sq[tid] += sq[tid + off]; }
        __syncthreads();
    }
    if (tid == 0) {
        atomicAdd(&g_stats[statoff + c], ss[0]);
        atomicAdd(&g_stats[statoff + nch + c], sq[0]);
    }
}

__global__ void k_bnfin32(const float* __restrict__ gl, const float* __restrict__ bl) {
    int o = threadIdx.x;
    float inv = 1.0f / (float)NPIX;
    float mean = g_stats[352 + o] * inv;
    float var = g_stats[384 + o] * inv - mean * mean;
    float sc = gl[o] * rsqrtf(fmaxf(var, 0.f) + 1e-5f);
    g_bn[256 + o] = sc;
    g_bn[288 + o] = bl[o] - mean * sc;
}

__global__ void __launch_bounds__(256) k_expand(const float* __restrict__ w1, const float* __restrict__ w2,
                                                const float* __restrict__ w3, const float* __restrict__ w4) {
    __shared__ float s_w[1024];
    __shared__ unsigned int s_out[256][33];
    int tid = threadIdx.x;
    {
        const float* ws[4] = {w1, w2, w3, w4};
        for (int e = tid; e < 1024; e += 256) s_w[e] = ws[e >> 8][e & 255];
    }
    __syncthreads();
    int idx = blockIdx.x * 256 + tid;
    float a[32];
#pragma unroll
    for (int q = 0; q < 32; q++) a[q] = g_a[(size_t)q * NPIX + idx];

#pragma unroll 1
    for (int di = 0; di < 4; di++) {
        float yv[32];
#pragma unroll
        for (int o = 0; o < 32; o++) {
            float s = 0.f;
            const float* wd = &s_w[di * 256 + o * 8];
#pragma unroll
            for (int k = 0; k < 8; k++) s = fmaf(a[di * 8 + k], wd[k], s);
            int ch = di * 32 + o;
            yv[o] = fmaxf(fmaf(s, g_bn[ch], g_bn[128 + ch]), 0.f);
        }
        __syncthreads();
#pragma unroll
        for (int j = 0; j < 16; j++) {
            __nv_bfloat16 h0 = __float2bfloat16_rn(yv[2 * j]);
            __nv_bfloat16 h1 = __float2bfloat16_rn(yv[2 * j + 1]);
            unsigned short l0 = __bfloat16_as_ushort(__float2bfloat16_rn(yv[2 * j] - __bfloat162float(h0)));
            unsigned short l1 = __bfloat16_as_ushort(__float2bfloat16_rn(yv[2 * j + 1] - __bfloat162float(h1)));
            s_out[tid][j] = (uint32_t)__bfloat16_as_ushort(h0) | ((uint32_t)__bfloat16_as_ushort(h1) << 16);
            s_out[tid][16 + j] = (uint32_t)l0 | ((uint32_t)l1 << 16);
        }
        __syncthreads();
        size_t base = (size_t)di * NPIX * 32 + (size_t)blockIdx.x * 256 * 32;
        for (int e = tid; e < 8192; e += 256)
            g_fbf[base + e] = s_out[e >> 5][e & 31];
    }
}

__global__ void k_final(const float* __restrict__ wf, float* __restrict__ out) {
    __shared__ float s_wf[1024];
    int tid = threadIdx.x;
#pragma unroll
    for (int it = 0; it < 4; it++) s_wf[tid + it * 256] = wf[tid + it * 256];
    __syncthreads();
    int idx = blockIdx.x * 256 + tid;
    int b = idx / HWC, p = idx - b * HWC;
    const float* hb = g_h + (size_t)b * SFC * HWC + p;
    float y[32];
#pragma unroll
    for (int c = 0; c < 32; c++) {
        float v = hb[(size_t)c * HWC];
        y[c] = fmaxf(fmaf(v, g_bn[256 + c], g_bn[288 + c]), 0.f);
    }
    float* op = out + (size_t)b * SFC * HWC + p;
#pragma unroll
    for (int o = 0; o < 32; o++) {
        float s = 0.f;
#pragma unroll
        for (int c = 0; c < 32; c++) s += y[c] * s_wf[o * 32 + c];
        op[(size_t)o * HWC] = s;
    }
}

__global__ void k_wprep2(const float* __restrict__ w_last) {
    int u = blockIdx.x * 256 + threadIdx.x;
    int tile = u / 3072;
    int ky = tile >> 2, chunk = tile & 3;
    int rem = u - tile * 3072;
    int idx = rem >> 6;
    int lr = rem & 63;
    int l = lr >> 1, r = lr & 1;
    int kx = idx >> 4;
    int s = (idx >> 2) & 3;
    int nt = idx & 3;
    int gid = l >> 2, tid4 = l & 3;
    int o = nt * 8 + gid;
    int kloc = 2 * tid4 + r * 8;
    int c0 = chunk * 32 + (s & 1) * 16 + kloc;
    int tap = ky * 3 + kx;
    float w0 = w_last[o * 1152 + c0 * 9 + tap];
    float w1 = w_last[o * 1152 + (c0 + 1) * 9 + tap];
    unsigned short q0, q1;
    if (s < 2) {
        q0 = __bfloat16_as_ushort(__float2bfloat16_rn(w0));
        q1 = __bfloat16_as_ushort(__float2bfloat16_rn(w1));
    } else {
        __nv_bfloat16 h0 = __float2bfloat16_rn(w0), h1 = __float2bfloat16_rn(w1);
        q0 = __bfloat16_as_ushort(__float2bfloat16_rn(w0 - __bfloat162float(h0)));
        q1 = __bfloat16_as_ushort(__float2bfloat16_rn(w1 - __bfloat162float(h1)));
    }
    g_wm[u] = (uint32_t)q0 | ((uint32_t)q1 << 16);
}

#define STG_BYTES 30720
#define SMEM_CONV (2 * STG_BYTES)

__global__ void __launch_bounds__(128) k_convmma2() {
    extern __shared__ __align__(16) char smem[];
    const uint32_t sbase = smem_u32(smem);
    int tid = threadIdx.x;
    int warp = tid >> 5, lane = tid & 31;
    int gid = lane >> 2, tid4 = lane & 3;
    int x0 = blockIdx.x * 126 - 1;
    int gy = blockIdx.y, b = blockIdx.z;

    float acc[2][12][4];
#pragma unroll
    for (int mt = 0; mt < 2; mt++)
#pragma unroll
        for (int n = 0; n < 12; n++)
#pragma unroll
            for (int e = 0; e < 4; e++) acc[mt][n][e] = 0.f;

#define LOAD_TILE(I) do { \
    int _ky = (I) >> 2, _ck = (I) & 3, _st = (I) & 1; \
    uint32_t _ab = sbase + _st * STG_BYTES; \
    uint32_t _bb = _ab + 18432; \
    int _yy = gy + _ky - 1; \
    int _gx = x0 + tid; \
    bool _ok = ((unsigned)_yy < HH) && ((unsigned)_gx < WW); \
    size_t _pix = (size_t)b * HWC + (size_t)(_ok ? _yy : 0) * WW + (_ok ? _gx : 0); \
    const char* _src = (const char*)g_fbf + ((size_t)_ck * NPIX + _pix) * 128; \
    uint32_t _dst = _ab + tid * 144; \
    int _sz = _ok ? 16 : 0; \
    _Pragma("unroll") \
    for (int _j = 0; _j < 8; _j++) \
        asm volatile("cp.async.cg.shared.global [%0], [%1], 16, %2;" \
                     :: "r"(_dst + _j * 16), "l"(_src + _j * 16), "r"(_sz)); \
    const char* _ws = (const char*)g_wm + (size_t)(I) * 12288; \
    _Pragma("unroll") \
    for (int _j = 0; _j < 6; _j++) { \
        int _off = (tid + _j * 128) * 16; \
        asm volatile("cp.async.cg.shared.global [%0], [%1], 16, 16;" \
                     :: "r"(_bb + _off), "l"(_ws + _off)); \
    } \
    asm volatile("cp.async.commit_group;"); \
} while (0)

    LOAD_TILE(0);

#pragma unroll 1
    for (int i = 0; i < 12; i++) {
        if (i + 1 < 12) {
            LOAD_TILE(i + 1);
            asm volatile("cp.async.wait_group 1;");
        } else {
            asm volatile("cp.async.wait_group 0;");
        }
        __syncthreads();
        int st = i & 1;
        const uint32_t* As = reinterpret_cast<const uint32_t*>(smem + st * STG_BYTES);
        const char* Bs = smem + st * STG_BYTES + 18432;

        uint32_t ar[4][2][4];
        {
            int r0 = warp * 32 + gid;
#pragma unroll
            for (int q = 0; q < 4; q++)
#pragma unroll
                for (int mt = 0; mt < 2; mt++) {
                    int row = r0 + mt * 16;
                    ar[q][mt][0] = As[row * 36 + q * 8 + tid4];
                    ar[q][mt][1] = As[(row + 8) * 36 + q * 8 + tid4];
                    ar[q][mt][2] = As[row * 36 + q * 8 + 4 + tid4];
                    ar[q][mt][3] = As[(row + 8) * 36 + q * 8 + 4 + tid4];
                }
        }
#pragma unroll
        for (int kx = 0; kx < 3; kx++) {
            uint32_t bw[4][4][2];
#pragma unroll
            for (int s = 0; s < 4; s++)
#pragma unroll
                for (int nt = 0; nt < 4; nt++) {
                    unsigned long long v = *reinterpret_cast<const unsigned long long*>(
                        Bs + ((kx * 4 + s) * 4 + nt) * 256 + lane * 8);
                    bw[s][nt][0] = (uint32_t)v;
                    bw[s][nt][1] = (uint32_t)(v >> 32);
                }
#pragma unroll
            for (int mt = 0; mt < 2; mt++)
#pragma unroll
                for (int nt = 0; nt < 4; nt++) {
                    float* c = acc[mt][kx * 4 + nt];
                    MMA16816(c, ar[0][mt], bw[0][nt][0], bw[0][nt][1]);
                    MMA16816(c, ar[1][mt], bw[1][nt][0], bw[1][nt][1]);
                    MMA16816(c, ar[0][mt], bw[2][nt][0], bw[2][nt][1]);
                    MMA16816(c, ar[1][mt], bw[3][nt][0], bw[3][nt][1]);
                    MMA16816(c, ar[2][mt], bw[0][nt][0], bw[0][nt][1]);
                    MMA16816(c, ar[3][mt], bw[1][nt][0], bw[1][nt][1]);
                }
        }
        __syncthreads();
    }

    float* S = reinterpret_cast<float*>(smem);
#pragma unroll
    for (int mt = 0; mt < 2; mt++)
#pragma unroll
        for (int ng = 0; ng < 12; ng++) {
            int row = warp * 32 + mt * 16 + gid;
            int col = ng * 8 + tid4 * 2;
            S[row * 100 + col]           = acc[mt][ng][0];
            S[row * 100 + col + 1]       = acc[mt][ng][1];
            S[(row + 8) * 100 + col]     = acc[mt][ng][2];
            S[(row + 8) * 100 + col + 1] = acc[mt][ng][3];
        }
    __syncthreads();

    int p = tid;
    int gx = x0 + p;
    if (p >= 1 && p <= 126 && gx < WW) {
        float* hp = g_h + (size_t)b * SFC * HWC + (size_t)gy * WW + gx;
#pragma unroll
        for (int o = 0; o < 32; o++) {
            float v = S[(p - 1) * 100 + o] + S[p * 100 + 32 + o] + S[(p + 1) * 100 + 64 + o];
            hp[(size_t)o * HWC] = v;
        }
    }
}

extern "C" void kernel_launch(void* const* d_in, const int* in_sizes, int n_in,
                              void* d_out, int out_size) {
    const float* x = nullptr;
    const float* w_last = nullptr;
    const float* w_fin = nullptr;
    const float* wN[4] = {nullptr, nullptr, nullptr, nullptr};
    const float* s32[10];
    int nw = 0, ns = 0;
    const int XSZ = (int)((size_t)BB * CIN * HWC);
    for (int i = 0; i < n_in; i++) {
        int sz = in_sizes[i];
        const float* ptr = (const float*)d_in[i];
        if (sz == XSZ) x = ptr;
        else if (sz == 32 * 128 * 9) w_last = ptr;
        else if (sz == 32 * 32) w_fin = ptr;
        else if (sz == 32 * 8) { if (nw < 4) wN[nw++] = ptr; }
        else if (sz == 32) { if (ns < 10) s32[ns++] = ptr; }
    }
    const float *g1, *b1, *g2, *b2, *g3, *b3, *g4, *b4, *g_last, *b_last;
    if (in_sizes[0] == XSZ) {
        g1 = s32[0]; b1 = s32[1]; g2 = s32[2]; b2 = s32[3];
        g3 = s32[4]; b3 = s32[5]; g4 = s32[6]; b4 = s32[7];
        g_last = s32[8]; b_last = s32[9];
    } else {
        b1 = s32[0]; b2 = s32[1]; b3 = s32[2]; b4 = s32[3]; b_last = s32[4];
        g1 = s32[5]; g2 = s32[6]; g3 = s32[7]; g4 = s32[8]; g_last = s32[9];
    }
    float* out = (float*)d_out;

    cudaFuncSetAttribute(k_convmma2, cudaFuncAttributeMaxDynamicSharedMemorySize, SMEM_CONV);

    k_zero<<<1, 512>>>();
    k_norm<<<NPIX / 256, 256>>>(x);
    k_aff<<<NPIX / 256, 256>>>();
    k_mom<<<dim3(4, 200), 256>>>();
    k_bnfin128<<<1, 128>>>(wN[0], wN[1], wN[2], wN[3], g1, b1, g2, b2, g3, b3, g4, b4);
    k_expand<<<NPIX / 256, 256>>>(wN[0], wN[1], wN[2], wN[3]);
    k_wprep2<<<144, 256>>>(w_last);
    k_convmma2<<<dim3(6, HH, BB), 128, SMEM_CONV>>>();
    k_stats<<<dim3(32, 25), 256>>>(1, 32, 352);
    k_bnfin32<<<1, 32>>>(g_last, b_last);
    k_final<<<NPIX / 256, 256>>>(w_fin, out);
}

// round 14
// speedup vs baseline: 1.0629x; 1.0629x over previous
#include <cuda_runtime.h>
#include <cuda_bf16.h>
#include <cstdint>

#define BB   4
#define CIN  32
#define HH   320
#define WW   640
#define HWC  (HH*WW)
#define NPIX (BB*HWC)
#define CCAT 128
#define SFC  32

// ---------------- device scratch ----------------
__device__ float g_xn[(size_t)NPIX * CIN];                          // planar normalized x
__device__ float g_a[(size_t)NPIX * 32];                            // planar clamped affinities [q][pix]
__device__ __align__(256) unsigned int g_fbf[(size_t)NPIX * CCAT];  // [chunk4][pix][32 u32: hi16|lo16]
__device__ float g_h[(size_t)NPIX * SFC];                           // planar pre-BN
__device__ __align__(128) unsigned int g_wm[36864];                 // mma-fragment-ordered weights
__device__ float g_stats[512];  // [di*44 + t] upper-tri M (t<36), [di*44+36+k] mean sums; [352..384) h sum; [384..416) h sumsq
__device__ float g_bn[512];     // [0..128) sc feats, [128..256) sh feats, [256..288) sc h, [288..320) sh h

__device__ __forceinline__ uint32_t smem_u32(const void* p) {
    uint32_t a;
    asm("{ .reg .u64 t; cvta.to.shared.u64 t, %1; cvt.u32.u64 %0, t; }" : "=r"(a) : "l"(p));
    return a;
}
#define MMA16816(c, a, b0v, b1v) \
    asm volatile("mma.sync.aligned.m16n8k16.row.col.f32.bf16.bf16.f32 " \
                 "{%0,%1,%2,%3},{%4,%5,%6,%7},{%8,%9},{%0,%1,%2,%3};" \
                 : "+f"((c)[0]), "+f"((c)[1]), "+f"((c)[2]), "+f"((c)[3]) \
                 : "r"((a)[0]), "r"((a)[1]), "r"((a)[2]), "r"((a)[3]), "r"(b0v), "r"(b1v))

__global__ void k_zero() { g_stats[threadIdx.x] = 0.f; }

__global__ void k_norm(const float* __restrict__ x) {
    int idx = blockIdx.x * 256 + threadIdx.x;
    int b = idx / HWC, p = idx - b * HWC;
    const float* xp = x + (size_t)b * CIN * HWC + p;
    float* op = g_xn + (size_t)b * CIN * HWC + p;
    float v[CIN]; float ss = 0.f;
#pragma unroll
    for (int c = 0; c < CIN; c++) { v[c] = xp[(size_t)c * HWC]; ss += v[c] * v[c]; }
    float rn = 1.f / fmaxf(sqrtf(ss), 1e-12f);
#pragma unroll
    for (int c = 0; c < CIN; c++) op[(size_t)c * HWC] = v[c] * rn;
}

__global__ void k_aff() {
    int idx = blockIdx.x * 256 + threadIdx.x;
    int b = idx / HWC, p = idx - b * HWC;
    int y = p / WW, xx = p - y * WW;
    const float* xb = g_xn + (size_t)b * CIN * HWC;
    float cv[CIN];
#pragma unroll
    for (int c = 0; c < CIN; c++) cv[c] = xb[(size_t)c * HWC + p];
    float a[32];
#pragma unroll 1
    for (int di = 0; di < 4; di++) {
        int d = 1 << di;
        int kk = 0;
#pragma unroll
        for (int iy = -1; iy <= 1; iy++)
#pragma unroll
            for (int jx = -1; jx <= 1; jx++) {
                if (iy == 0 && jx == 0) continue;
                int ny = y + iy * d, nx = xx + jx * d;
                float dot = 0.f;
                if ((unsigned)ny < HH && (unsigned)nx < WW) {
                    int np = ny * WW + nx;
#pragma unroll
                    for (int c = 0; c < CIN; c++) dot += cv[c] * xb[(size_t)c * HWC + np];
                }
                a[di * 8 + kk] = fmaxf(dot, 0.f);
                kk++;
            }
    }
#pragma unroll
    for (int n = 0; n < 32; n++) g_a[(size_t)n * NPIX + idx] = a[n];
}

// affinity moments per branch: Sum a_j (8) + upper-triangle Sum a_j*a_k (36). 200 CTAs.
__global__ void __launch_bounds__(256) k_mom() {
    int di = blockIdx.x;          // branch
    int slice = blockIdx.y;       // 50 slices of 16384 px
    int tid = threadIdx.x;
    int lane = tid & 31;
    float m[8];
    float M[36];
#pragma unroll
    for (int j = 0; j < 8; j++) m[j] = 0.f;
#pragma unroll
    for (int t = 0; t < 36; t++) M[t] = 0.f;
    int e0 = slice * 16384;
    for (int e = e0 + tid; e < e0 + 16384; e += 256) {
        float av[8];
#pragma unroll
        for (int k = 0; k < 8; k++) av[k] = g_a[(size_t)(di * 8 + k) * NPIX + e];
        int t = 0;
#pragma unroll
        for (int j = 0; j < 8; j++) {
            m[j] += av[j];
#pragma unroll
            for (int k = j; k < 8; k++) { M[t] = fmaf(av[j], av[k], M[t]); t++; }
        }
    }
#pragma unroll
    for (int t = 0; t < 36; t++) {
        float w = M[t];
#pragma unroll
        for (int off = 16; off > 0; off >>= 1) w += __shfl_xor_sync(0xffffffffu, w, off);
        if (lane == 0) atomicAdd(&g_stats[di * 44 + t], w);
    }
#pragma unroll
    for (int j = 0; j < 8; j++) {
        float v = m[j];
#pragma unroll
        for (int off = 16; off > 0; off >>= 1) v += __shfl_xor_sync(0xffffffffu, v, off);
        if (lane == 0) atomicAdd(&g_stats[di * 44 + 36 + j], v);
    }
}

// BN coefficients for the 128 feature channels, from symmetric affinity moments
__global__ void k_bnfin128(const float* __restrict__ w1, const float* __restrict__ w2,
                           const float* __restrict__ w3, const float* __restrict__ w4,
                           const float* __restrict__ g1, const float* __restrict__ b1,
                           const float* __restrict__ g2, const float* __restrict__ b2,
                           const float* __restrict__ g3, const float* __restrict__ b3,
                           const float* __restrict__ g4, const float* __restrict__ b4) {
    int c = threadIdx.x;
    int di = c >> 5, o = c & 31;
    const float* ws[4] = {w1, w2, w3, w4};
    const float* gs[4] = {g1, g2, g3, g4};
    const float* bs[4] = {b1, b2, b3, b4};
    float inv = 1.0f / (float)NPIX;
    const float* w = ws[di] + o * 8;
    const float* st = &g_stats[di * 44];
    float mean = 0.f;
#pragma unroll
    for (int k = 0; k < 8; k++) mean = fmaf(w[k], st[36 + k] * inv, mean);
    float ehh = 0.f;
    int t = 0;
#pragma unroll
    for (int j = 0; j < 8; j++) {
#pragma unroll
        for (int k = j; k < 8; k++) {
            float coef = (k == j) ? (w[j] * w[j]) : (2.f * w[j] * w[k]);
            ehh = fmaf(coef, st[t], ehh);
            t++;
        }
    }
    ehh *= inv;
    float var = ehh - mean * mean;
    float sc = gs[di][o] * rsqrtf(fmaxf(var, 0.f) + 1e-5f);
    g_bn[c] = sc;
    g_bn[128 + c] = bs[di][o] - mean * sc;
}

__global__ void k_stats(int which, int nch, int statoff) {
    const float* buf = which ? g_h : g_a;
    int c = blockIdx.x, slice = blockIdx.y, tid = threadIdx.x;
    const int P4 = HWC / 4;
    float s = 0.f, q = 0.f;
    int e0 = slice * 8192;
    for (int e = e0 + tid; e < e0 + 8192; e += 256) {
        int b = e / P4, p4 = e - b * P4;
        const float4* plane = reinterpret_cast<const float4*>(buf + ((size_t)b * nch + c) * HWC);
        float4 v = plane[p4];
        s += v.x + v.y + v.z + v.w;
        q += v.x * v.x + v.y * v.y + v.z * v.z + v.w * v.w;
    }
    __shared__ float ss[256], sq[256];
    ss[tid] = s; sq[tid] = q;
    __syncthreads();
    for (int off = 128; off > 0; off >>= 1) {
        if (tid < off) { ss[tid] += ss[tid + off]; sq[tid] += sq[tid + off]; }
        __syncthreads();
    }
    if (tid == 0) {
        atomicAdd(&g_stats[statoff + c], ss[0]);
        atomicAdd(&g_stats[statoff + nch + c], sq[0]);
    }
}

__global__ void k_bnfin32(const float* __restrict__ gl, const float* __restrict__ bl) {
    int o = threadIdx.x;
    float inv = 1.0f / (float)NPIX;
    float mean = g_stats[352 + o] * inv;
    float var = g_stats[384 + o] * inv - mean * mean;
    float sc = gl[o] * rsqrtf(fmaxf(var, 0.f) + 1e-5f);
    g_bn[256 + o] = sc;
    g_bn[288 + o] = bl[o] - mean * sc;
}

__global__ void __launch_bounds__(256) k_expand(const float* __restrict__ w1, const float* __restrict__ w2,
                                                const float* __restrict__ w3, const float* __restrict__ w4) {
    __shared__ float s_w[1024];
    __shared__ unsigned int s_out[256][33];
    int tid = threadIdx.x;
    {
        const float* ws[4] = {w1, w2, w3, w4};
        for (int e = tid; e < 1024; e += 256) s_w[e] = ws[e >> 8][e & 255];
    }
    __syncthreads();
    int idx = blockIdx.x * 256 + tid;
    float a[32];
#pragma unroll
    for (int q = 0; q < 32; q++) a[q] = g_a[(size_t)q * NPIX + idx];

#pragma unroll 1
    for (int di = 0; di < 4; di++) {
        float yv[32];
#pragma unroll
        for (int o = 0; o < 32; o++) {
            float s = 0.f;
            const float* wd = &s_w[di * 256 + o * 8];
#pragma unroll
            for (int k = 0; k < 8; k++) s = fmaf(a[di * 8 + k], wd[k], s);
            int ch = di * 32 + o;
            yv[o] = fmaxf(fmaf(s, g_bn[ch], g_bn[128 + ch]), 0.f);
        }
        __syncthreads();
#pragma unroll
        for (int j = 0; j < 16; j++) {
            __nv_bfloat16 h0 = __float2bfloat16_rn(yv[2 * j]);
            __nv_bfloat16 h1 = __float2bfloat16_rn(yv[2 * j + 1]);
            unsigned short l0 = __bfloat16_as_ushort(__float2bfloat16_rn(yv[2 * j] - __bfloat162float(h0)));
            unsigned short l1 = __bfloat16_as_ushort(__float2bfloat16_rn(yv[2 * j + 1] - __bfloat162float(h1)));
            s_out[tid][j] = (uint32_t)__bfloat16_as_ushort(h0) | ((uint32_t)__bfloat16_as_ushort(h1) << 16);
            s_out[tid][16 + j] = (uint32_t)l0 | ((uint32_t)l1 << 16);
        }
        __syncthreads();
        size_t base = (size_t)di * NPIX * 32 + (size_t)blockIdx.x * 256 * 32;
        for (int e = tid; e < 8192; e += 256)
            g_fbf[base + e] = s_out[e >> 5][e & 31];
    }
}

__global__ void k_final(const float* __restrict__ wf, float* __restrict__ out) {
    __shared__ float s_wf[1024];
    int tid = threadIdx.x;
#pragma unroll
    for (int it = 0; it < 4; it++) s_wf[tid + it * 256] = wf[tid + it * 256];
    __syncthreads();
    int idx = blockIdx.x * 256 + tid;
    int b = idx / HWC, p = idx - b * HWC;
    const float* hb = g_h + (size_t)b * SFC * HWC + p;
    float y[32];
#pragma unroll
    for (int c = 0; c < 32; c++) {
        float v = hb[(size_t)c * HWC];
        y[c] = fmaxf(fmaf(v, g_bn[256 + c], g_bn[288 + c]), 0.f);
    }
    float* op = out + (size_t)b * SFC * HWC + p;
#pragma unroll
    for (int o = 0; o < 32; o++) {
        float s = 0.f;
#pragma unroll
        for (int c = 0; c < 32; c++) s += y[c] * s_wf[o * 32 + c];
        op[(size_t)o * HWC] = s;
    }
}

__global__ void k_wprep2(const float* __restrict__ w_last) {
    int u = blockIdx.x * 256 + threadIdx.x;
    int tile = u / 3072;
    int ky = tile >> 2, chunk = tile & 3;
    int rem = u - tile * 3072;
    int idx = rem >> 6;
    int lr = rem & 63;
    int l = lr >> 1, r = lr & 1;
    int kx = idx >> 4;
    int s = (idx >> 2) & 3;
    int nt = idx & 3;
    int gid = l >> 2, tid4 = l & 3;
    int o = nt * 8 + gid;
    int kloc = 2 * tid4 + r * 8;
    int c0 = chunk * 32 + (s & 1) * 16 + kloc;
    int tap = ky * 3 + kx;
    float w0 = w_last[o * 1152 + c0 * 9 + tap];
    float w1 = w_last[o * 1152 + (c0 + 1) * 9 + tap];
    unsigned short q0, q1;
    if (s < 2) {
        q0 = __bfloat16_as_ushort(__float2bfloat16_rn(w0));
        q1 = __bfloat16_as_ushort(__float2bfloat16_rn(w1));
    } else {
        __nv_bfloat16 h0 = __float2bfloat16_rn(w0), h1 = __float2bfloat16_rn(w1);
        q0 = __bfloat16_as_ushort(__float2bfloat16_rn(w0 - __bfloat162float(h0)));
        q1 = __bfloat16_as_ushort(__float2bfloat16_rn(w1 - __bfloat162float(h1)));
    }
    g_wm[u] = (uint32_t)q0 | ((uint32_t)q1 << 16);
}

#define STG_BYTES 30720
#define SMEM_CONV (2 * STG_BYTES)

__global__ void __launch_bounds__(128) k_convmma2() {
    extern __shared__ __align__(16) char smem[];
    const uint32_t sbase = smem_u32(smem);
    int tid = threadIdx.x;
    int warp = tid >> 5, lane = tid & 31;
    int gid = lane >> 2, tid4 = lane & 3;
    int x0 = blockIdx.x * 126 - 1;
    int gy = blockIdx.y, b = blockIdx.z;

    float acc[2][12][4];
#pragma unroll
    for (int mt = 0; mt < 2; mt++)
#pragma unroll
        for (int n = 0; n < 12; n++)
#pragma unroll
            for (int e = 0; e < 4; e++) acc[mt][n][e] = 0.f;

#define LOAD_TILE(I) do { \
    int _ky = (I) >> 2, _ck = (I) & 3, _st = (I) & 1; \
    uint32_t _ab = sbase + _st * STG_BYTES; \
    uint32_t _bb = _ab + 18432; \
    int _yy = gy + _ky - 1; \
    int _gx = x0 + tid; \
    bool _ok = ((unsigned)_yy < HH) && ((unsigned)_gx < WW); \
    size_t _pix = (size_t)b * HWC + (size_t)(_ok ? _yy : 0) * WW + (_ok ? _gx : 0); \
    const char* _src = (const char*)g_fbf + ((size_t)_ck * NPIX + _pix) * 128; \
    uint32_t _dst = _ab + tid * 144; \
    int _sz = _ok ? 16 : 0; \
    _Pragma("unroll") \
    for (int _j = 0; _j < 8; _j++) \
        asm volatile("cp.async.cg.shared.global [%0], [%1], 16, %2;" \
                     :: "r"(_dst + _j * 16), "l"(_src + _j * 16), "r"(_sz)); \
    const char* _ws = (const char*)g_wm + (size_t)(I) * 12288; \
    _Pragma("unroll") \
    for (int _j = 0; _j < 6; _j++) { \
        int _off = (tid + _j * 128) * 16; \
        asm volatile("cp.async.cg.shared.global [%0], [%1], 16, 16;" \
                     :: "r"(_bb + _off), "l"(_ws + _off)); \
    } \
    asm volatile("cp.async.commit_group;"); \
} while (0)

    LOAD_TILE(0);

#pragma unroll 1
    for (int i = 0; i < 12; i++) {
        if (i + 1 < 12) {
            LOAD_TILE(i + 1);
            asm volatile("cp.async.wait_group 1;");
        } else {
            asm volatile("cp.async.wait_group 0;");
        }
        __syncthreads();
        int st = i & 1;
        const uint32_t* As = reinterpret_cast<const uint32_t*>(smem + st * STG_BYTES);
        const char* Bs = smem + st * STG_BYTES + 18432;

        uint32_t ar[4][2][4];
        {
            int r0 = warp * 32 + gid;
#pragma unroll
            for (int q = 0; q < 4; q++)
#pragma unroll
                for (int mt = 0; mt < 2; mt++) {
                    int row = r0 + mt * 16;
                    ar[q][mt][0] = As[row * 36 + q * 8 + tid4];
                    ar[q][mt][1] = As[(row + 8) * 36 + q * 8 + tid4];
                    ar[q][mt][2] = As[row * 36 + q * 8 + 4 + tid4];
                    ar[q][mt][3] = As[(row + 8) * 36 + q * 8 + 4 + tid4];
                }
        }
#pragma unroll
        for (int kx = 0; kx < 3; kx++) {
            uint32_t bw[4][4][2];
#pragma unroll
            for (int s = 0; s < 4; s++)
#pragma unroll
                for (int nt = 0; nt < 4; nt++) {
                    unsigned long long v = *reinterpret_cast<const unsigned long long*>(
                        Bs + ((kx * 4 + s) * 4 + nt) * 256 + lane * 8);
                    bw[s][nt][0] = (uint32_t)v;
                    bw[s][nt][1] = (uint32_t)(v >> 32);
                }
#pragma unroll
            for (int mt = 0; mt < 2; mt++)
#pragma unroll
                for (int nt = 0; nt < 4; nt++) {
                    float* c = acc[mt][kx * 4 + nt];
                    MMA16816(c, ar[0][mt], bw[0][nt][0], bw[0][nt][1]);
                    MMA16816(c, ar[1][mt], bw[1][nt][0], bw[1][nt][1]);
                    MMA16816(c, ar[0][mt], bw[2][nt][0], bw[2][nt][1]);
                    MMA16816(c, ar[1][mt], bw[3][nt][0], bw[3][nt][1]);
                    MMA16816(c, ar[2][mt], bw[0][nt][0], bw[0][nt][1]);
                    MMA16816(c, ar[3][mt], bw[1][nt][0], bw[1][nt][1]);
                }
        }
        __syncthreads();
    }

    float* S = reinterpret_cast<float*>(smem);
#pragma unroll
    for (int mt = 0; mt < 2; mt++)
#pragma unroll
        for (int ng = 0; ng < 12; ng++) {
            int row = warp * 32 + mt * 16 + gid;
            int col = ng * 8 + tid4 * 2;
            S[row * 100 + col]           = acc[mt][ng][0];
            S[row * 100 + col + 1]       = acc[mt][ng][1];
            S[(row + 8) * 100 + col]     = acc[mt][ng][2];
            S[(row + 8) * 100 + col + 1] = acc[mt][ng][3];
        }
    __syncthreads();

    int p = tid;
    int gx = x0 + p;
    if (p >= 1 && p <= 126 && gx < WW) {
        float* hp = g_h + (size_t)b * SFC * HWC + (size_t)gy * WW + gx;
#pragma unroll
        for (int o = 0; o < 32; o++) {
            float v = S[(p - 1) * 100 + o] + S[p * 100 + 32 + o] + S[(p + 1) * 100 + 64 + o];
            hp[(size_t)o * HWC] = v;
        }
    }
}

extern "C" void kernel_launch(void* const* d_in, const int* in_sizes, int n_in,
                              void* d_out, int out_size) {
    const float* x = nullptr;
    const float* w_last = nullptr;
    const float* w_fin = nullptr;
    const float* wN[4] = {nullptr, nullptr, nullptr, nullptr};
    const float* s32[10];
    int nw = 0, ns = 0;
    const int XSZ = (int)((size_t)BB * CIN * HWC);
    for (int i = 0; i < n_in; i++) {
        int sz = in_sizes[i];
        const float* ptr = (const float*)d_in[i];
        if (sz == XSZ) x = ptr;
        else if (sz == 32 * 128 * 9) w_last = ptr;
        else if (sz == 32 * 32) w_fin = ptr;
        else if (sz == 32 * 8) { if (nw < 4) wN[nw++] = ptr; }
        else if (sz == 32) { if (ns < 10) s32[ns++] = ptr; }
    }
    const float *g1, *b1, *g2, *b2, *g3, *b3, *g4, *b4, *g_last, *b_last;
    if (in_sizes[0] == XSZ) {
        g1 = s32[0]; b1 = s32[1]; g2 = s32[2]; b2 = s32[3];
        g3 = s32[4]; b3 = s32[5]; g4 = s32[6]; b4 = s32[7];
        g_last = s32[8]; b_last = s32[9];
    } else {
        b1 = s32[0]; b2 = s32[1]; b3 = s32[2]; b4 = s32[3]; b_last = s32[4];
        g1 = s32[5]; g2 = s32[6]; g3 = s32[7]; g4 = s32[8]; g_last = s32[9];
    }
    float* out = (float*)d_out;

    cudaFuncSetAttribute(k_convmma2, cudaFuncAttributeMaxDynamicSharedMemorySize, SMEM_CONV);

    k_zero<<<1, 512>>>();
    k_norm<<<NPIX / 256, 256>>>(x);
    k_aff<<<NPIX / 256, 256>>>();
    k_mom<<<dim3(4, 50), 256>>>();
    k_bnfin128<<<1, 128>>>(wN[0], wN[1], wN[2], wN[3], g1, b1, g2, b2, g3, b3, g4, b4);
    k_expand<<<NPIX / 256, 256>>>(wN[0], wN[1], wN[2], wN[3]);
    k_wprep2<<<144, 256>>>(w_last);
    k_convmma2<<<dim3(6, HH, BB), 128, SMEM_CONV>>>();
    k_stats<<<dim3(32, 25), 256>>>(1, 32, 352);
    k_bnfin32<<<1, 32>>>(g_last, b_last);
    k_final<<<NPIX / 256, 256>>>(w_fin, out);
}

// round 15
// speedup vs baseline: 1.0721x; 1.0087x over previous
#include <cuda_runtime.h>
#include <cuda_bf16.h>
#include <cstdint>

#define BB   4
#define CIN  32
#define HH   320
#define WW   640
#define HWC  (HH*WW)
#define NPIX (BB*HWC)
#define CCAT 128
#define SFC  32

// ---------------- device scratch ----------------
__device__ float g_xn[(size_t)NPIX * CIN];                          // planar normalized x
__device__ __align__(16) float g_a[(size_t)NPIX * 32];              // planar clamped affinities [q][pix]
__device__ __align__(256) unsigned int g_fbf[(size_t)NPIX * CCAT];  // [chunk4][pix][32 u32: hi16|lo16]
__device__ float g_h[(size_t)NPIX * SFC];                           // planar pre-BN
__device__ __align__(128) unsigned int g_wm[36864];                 // mma-fragment-ordered weights
__device__ float g_stats[512];  // [di*44 + t] upper-tri M (t<36), [di*44+36+k] mean sums; [352..384) h sum; [384..416) h sumsq
__device__ float g_bn[512];     // [0..128) sc feats, [128..256) sh feats, [256..288) sc h, [288..320) sh h

__device__ __forceinline__ uint32_t smem_u32(const void* p) {
    uint32_t a;
    asm("{ .reg .u64 t; cvta.to.shared.u64 t, %1; cvt.u32.u64 %0, t; }" : "=r"(a) : "l"(p));
    return a;
}
#define MMA16816(c, a, b0v, b1v) \
    asm volatile("mma.sync.aligned.m16n8k16.row.col.f32.bf16.bf16.f32 " \
                 "{%0,%1,%2,%3},{%4,%5,%6,%7},{%8,%9},{%0,%1,%2,%3};" \
                 : "+f"((c)[0]), "+f"((c)[1]), "+f"((c)[2]), "+f"((c)[3]) \
                 : "r"((a)[0]), "r"((a)[1]), "r"((a)[2]), "r"((a)[3]), "r"(b0v), "r"(b1v))

__global__ void k_zero() { g_stats[threadIdx.x] = 0.f; }

__global__ void k_norm(const float* __restrict__ x) {
    int idx = blockIdx.x * 256 + threadIdx.x;
    int b = idx / HWC, p = idx - b * HWC;
    const float* xp = x + (size_t)b * CIN * HWC + p;
    float* op = g_xn + (size_t)b * CIN * HWC + p;
    float v[CIN]; float ss = 0.f;
#pragma unroll
    for (int c = 0; c < CIN; c++) { v[c] = xp[(size_t)c * HWC]; ss += v[c] * v[c]; }
    float rn = 1.f / fmaxf(sqrtf(ss), 1e-12f);
#pragma unroll
    for (int c = 0; c < CIN; c++) op[(size_t)c * HWC] = v[c] * rn;
}

__global__ void k_aff() {
    int idx = blockIdx.x * 256 + threadIdx.x;
    int b = idx / HWC, p = idx - b * HWC;
    int y = p / WW, xx = p - y * WW;
    const float* xb = g_xn + (size_t)b * CIN * HWC;
    float cv[CIN];
#pragma unroll
    for (int c = 0; c < CIN; c++) cv[c] = xb[(size_t)c * HWC + p];
    float a[32];
#pragma unroll 1
    for (int di = 0; di < 4; di++) {
        int d = 1 << di;
        int kk = 0;
#pragma unroll
        for (int iy = -1; iy <= 1; iy++)
#pragma unroll
            for (int jx = -1; jx <= 1; jx++) {
                if (iy == 0 && jx == 0) continue;
                int ny = y + iy * d, nx = xx + jx * d;
                float dot = 0.f;
                if ((unsigned)ny < HH && (unsigned)nx < WW) {
                    int np = ny * WW + nx;
#pragma unroll
                    for (int c = 0; c < CIN; c++) dot += cv[c] * xb[(size_t)c * HWC + np];
                }
                a[di * 8 + kk] = fmaxf(dot, 0.f);
                kk++;
            }
    }
#pragma unroll
    for (int n = 0; n < 32; n++) g_a[(size_t)n * NPIX + idx] = a[n];
}

// affinity moments per branch: Sum a_j (8) + upper-tri Sum a_j*a_k (36). float4 pixels, 400 CTAs.
__global__ void __launch_bounds__(256) k_mom() {
    int di = blockIdx.x;          // branch
    int slice = blockIdx.y;       // 100 slices of 2048 float4 (8192 px)
    int tid = threadIdx.x;
    int lane = tid & 31;
    float m[8];
    float M[36];
#pragma unroll
    for (int j = 0; j < 8; j++) m[j] = 0.f;
#pragma unroll
    for (int t = 0; t < 36; t++) M[t] = 0.f;
    const int NP4 = NPIX / 4;
    int e0 = slice * 2048;
    for (int e = e0 + tid; e < e0 + 2048; e += 256) {
        float4 av[8];
#pragma unroll
        for (int k = 0; k < 8; k++)
            av[k] = reinterpret_cast<const float4*>(g_a)[(size_t)(di * 8 + k) * NP4 + e];
        int t = 0;
#pragma unroll
        for (int j = 0; j < 8; j++) {
            m[j] += (av[j].x + av[j].y) + (av[j].z + av[j].w);
#pragma unroll
            for (int k = j; k < 8; k++) {
                float s = av[j].x * av[k].x;
                s = fmaf(av[j].y, av[k].y, s);
                s = fmaf(av[j].z, av[k].z, s);
                s = fmaf(av[j].w, av[k].w, s);
                M[t] += s;
                t++;
            }
        }
    }
#pragma unroll
    for (int t = 0; t < 36; t++) {
        float w = M[t];
#pragma unroll
        for (int off = 16; off > 0; off >>= 1) w += __shfl_xor_sync(0xffffffffu, w, off);
        if (lane == 0) atomicAdd(&g_stats[di * 44 + t], w);
    }
#pragma unroll
    for (int j = 0; j < 8; j++) {
        float v = m[j];
#pragma unroll
        for (int off = 16; off > 0; off >>= 1) v += __shfl_xor_sync(0xffffffffu, v, off);
        if (lane == 0) atomicAdd(&g_stats[di * 44 + 36 + j], v);
    }
}

// BN coefficients for the 128 feature channels, from symmetric affinity moments
__global__ void k_bnfin128(const float* __restrict__ w1, const float* __restrict__ w2,
                           const float* __restrict__ w3, const float* __restrict__ w4,
                           const float* __restrict__ g1, const float* __restrict__ b1,
                           const float* __restrict__ g2, const float* __restrict__ b2,
                           const float* __restrict__ g3, const float* __restrict__ b3,
                           const float* __restrict__ g4, const float* __restrict__ b4) {
    int c = threadIdx.x;
    int di = c >> 5, o = c & 31;
    const float* ws[4] = {w1, w2, w3, w4};
    const float* gs[4] = {g1, g2, g3, g4};
    const float* bs[4] = {b1, b2, b3, b4};
    float inv = 1.0f / (float)NPIX;
    const float* w = ws[di] + o * 8;
    const float* st = &g_stats[di * 44];
    float mean = 0.f;
#pragma unroll
    for (int k = 0; k < 8; k++) mean = fmaf(w[k], st[36 + k] * inv, mean);
    float ehh = 0.f;
    int t = 0;
#pragma unroll
    for (int j = 0; j < 8; j++) {
#pragma unroll
        for (int k = j; k < 8; k++) {
            float coef = (k == j) ? (w[j] * w[j]) : (2.f * w[j] * w[k]);
            ehh = fmaf(coef, st[t], ehh);
            t++;
        }
    }
    ehh *= inv;
    float var = ehh - mean * mean;
    float sc = gs[di][o] * rsqrtf(fmaxf(var, 0.f) + 1e-5f);
    g_bn[c] = sc;
    g_bn[128 + c] = bs[di][o] - mean * sc;
}

__global__ void k_stats(int which, int nch, int statoff) {
    const float* buf = which ? g_h : g_a;
    int c = blockIdx.x, slice = blockIdx.y, tid = threadIdx.x;
    const int P4 = HWC / 4;
    float s = 0.f, q = 0.f;
    int e0 = slice * 8192;
    for (int e = e0 + tid; e < e0 + 8192; e += 256) {
        int b = e / P4, p4 = e - b * P4;
        const float4* plane = reinterpret_cast<const float4*>(buf + ((size_t)b * nch + c) * HWC);
        float4 v = plane[p4];
        s += v.x + v.y + v.z + v.w;
        q += v.x * v.x + v.y * v.y + v.z * v.z + v.w * v.w;
    }
    __shared__ float ss[256], sq[256];
    ss[tid] = s; sq[tid] = q;
    __syncthreads();
    for (int off = 128; off > 0; off >>= 1) {
        if (tid < off) { ss[tid] += ss[tid + off]; sq[tid] += sq[tid + off]; }
        __syncthreads();
    }
    if (tid == 0) {
        atomicAdd(&g_stats[statoff + c], ss[0]);
        atomicAdd(&g_stats[statoff + nch + c], sq[0]);
    }
}

__global__ void k_bnfin32(const float* __restrict__ gl, const float* __restrict__ bl) {
    int o = threadIdx.x;
    float inv = 1.0f / (float)NPIX;
    float mean = g_stats[352 + o] * inv;
    float var = g_stats[384 + o] * inv - mean * mean;
    float sc = gl[o] * rsqrtf(fmaxf(var, 0.f) + 1e-5f);
    g_bn[256 + o] = sc;
    g_bn[288 + o] = bl[o] - mean * sc;
}

__global__ void __launch_bounds__(256) k_expand(const float* __restrict__ w1, const float* __restrict__ w2,
                                                const float* __restrict__ w3, const float* __restrict__ w4) {
    __shared__ float s_w[1024];
    __shared__ unsigned int s_out[256][33];
    int tid = threadIdx.x;
    {
        const float* ws[4] = {w1, w2, w3, w4};
        for (int e = tid; e < 1024; e += 256) s_w[e] = ws[e >> 8][e & 255];
    }
    __syncthreads();
    int idx = blockIdx.x * 256 + tid;
    float a[32];
#pragma unroll
    for (int q = 0; q < 32; q++) a[q] = g_a[(size_t)q * NPIX + idx];

#pragma unroll 1
    for (int di = 0; di < 4; di++) {
        float yv[32];
#pragma unroll
        for (int o = 0; o < 32; o++) {
            float s = 0.f;
            const float* wd = &s_w[di * 256 + o * 8];
#pragma unroll
            for (int k = 0; k < 8; k++) s = fmaf(a[di * 8 + k], wd[k], s);
            int ch = di * 32 + o;
            yv[o] = fmaxf(fmaf(s, g_bn[ch], g_bn[128 + ch]), 0.f);
        }
        __syncthreads();
#pragma unroll
        for (int j = 0; j < 16; j++) {
            __nv_bfloat16 h0 = __float2bfloat16_rn(yv[2 * j]);
            __nv_bfloat16 h1 = __float2bfloat16_rn(yv[2 * j + 1]);
            unsigned short l0 = __bfloat16_as_ushort(__float2bfloat16_rn(yv[2 * j] - __bfloat162float(h0)));
            unsigned short l1 = __bfloat16_as_ushort(__float2bfloat16_rn(yv[2 * j + 1] - __bfloat162float(h1)));
            s_out[tid][j] = (uint32_t)__bfloat16_as_ushort(h0) | ((uint32_t)__bfloat16_as_ushort(h1) << 16);
            s_out[tid][16 + j] = (uint32_t)l0 | ((uint32_t)l1 << 16);
        }
        __syncthreads();
        size_t base = (size_t)di * NPIX * 32 + (size_t)blockIdx.x * 256 * 32;
        for (int e = tid; e < 8192; e += 256)
            g_fbf[base + e] = s_out[e >> 5][e & 31];
    }
}

__global__ void k_final(const float* __restrict__ wf, float* __restrict__ out) {
    __shared__ float s_wf[1024];
    int tid = threadIdx.x;
#pragma unroll
    for (int it = 0; it < 4; it++) s_wf[tid + it * 256] = wf[tid + it * 256];
    __syncthreads();
    int idx = blockIdx.x * 256 + tid;
    int b = idx / HWC, p = idx - b * HWC;
    const float* hb = g_h + (size_t)b * SFC * HWC + p;
    float y[32];
#pragma unroll
    for (int c = 0; c < 32; c++) {
        float v = hb[(size_t)c * HWC];
        y[c] = fmaxf(fmaf(v, g_bn[256 + c], g_bn[288 + c]), 0.f);
    }
    float* op = out + (size_t)b * SFC * HWC + p;
#pragma unroll
    for (int o = 0; o < 32; o++) {
        float s = 0.f;
#pragma unroll
        for (int c = 0; c < 32; c++) s += y[c] * s_wf[o * 32 + c];
        op[(size_t)o * HWC] = s;
    }
}

__global__ void k_wprep2(const float* __restrict__ w_last) {
    int u = blockIdx.x * 256 + threadIdx.x;
    int tile = u / 3072;
    int ky = tile >> 2, chunk = tile & 3;
    int rem = u - tile * 3072;
    int idx = rem >> 6;
    int lr = rem & 63;
    int l = lr >> 1, r = lr & 1;
    int kx = idx >> 4;
    int s = (idx >> 2) & 3;
    int nt = idx & 3;
    int gid = l >> 2, tid4 = l & 3;
    int o = nt * 8 + gid;
    int kloc = 2 * tid4 + r * 8;
    int c0 = chunk * 32 + (s & 1) * 16 + kloc;
    int tap = ky * 3 + kx;
    float w0 = w_last[o * 1152 + c0 * 9 + tap];
    float w1 = w_last[o * 1152 + (c0 + 1) * 9 + tap];
    unsigned short q0, q1;
    if (s < 2) {
        q0 = __bfloat16_as_ushort(__float2bfloat16_rn(w0));
        q1 = __bfloat16_as_ushort(__float2bfloat16_rn(w1));
    } else {
        __nv_bfloat16 h0 = __float2bfloat16_rn(w0), h1 = __float2bfloat16_rn(w1);
        q0 = __bfloat16_as_ushort(__float2bfloat16_rn(w0 - __bfloat162float(h0)));
        q1 = __bfloat16_as_ushort(__float2bfloat16_rn(w1 - __bfloat162float(h1)));
    }
    g_wm[u] = (uint32_t)q0 | ((uint32_t)q1 << 16);
}

#define STG_BYTES 30720
#define SMEM_CONV (2 * STG_BYTES)

__global__ void __launch_bounds__(128) k_convmma2() {
    extern __shared__ __align__(16) char smem[];
    const uint32_t sbase = smem_u32(smem);
    int tid = threadIdx.x;
    int warp = tid >> 5, lane = tid & 31;
    int gid = lane >> 2, tid4 = lane & 3;
    int x0 = blockIdx.x * 126 - 1;
    int gy = blockIdx.y, b = blockIdx.z;

    float acc[2][12][4];
#pragma unroll
    for (int mt = 0; mt < 2; mt++)
#pragma unroll
        for (int n = 0; n < 12; n++)
#pragma unroll
            for (int e = 0; e < 4; e++) acc[mt][n][e] = 0.f;

#define LOAD_TILE(I) do { \
    int _ky = (I) >> 2, _ck = (I) & 3, _st = (I) & 1; \
    uint32_t _ab = sbase + _st * STG_BYTES; \
    uint32_t _bb = _ab + 18432; \
    int _yy = gy + _ky - 1; \
    int _gx = x0 + tid; \
    bool _ok = ((unsigned)_yy < HH) && ((unsigned)_gx < WW); \
    size_t _pix = (size_t)b * HWC + (size_t)(_ok ? _yy : 0) * WW + (_ok ? _gx : 0); \
    const char* _src = (const char*)g_fbf + ((size_t)_ck * NPIX + _pix) * 128; \
    uint32_t _dst = _ab + tid * 144; \
    int _sz = _ok ? 16 : 0; \
    _Pragma("unroll") \
    for (int _j = 0; _j < 8; _j++) \
        asm volatile("cp.async.cg.shared.global [%0], [%1], 16, %2;" \
                     :: "r"(_dst + _j * 16), "l"(_src + _j * 16), "r"(_sz)); \
    const char* _ws = (const char*)g_wm + (size_t)(I) * 12288; \
    _Pragma("unroll") \
    for (int _j = 0; _j < 6; _j++) { \
        int _off = (tid + _j * 128) * 16; \
        asm volatile("cp.async.cg.shared.global [%0], [%1], 16, 16;" \
                     :: "r"(_bb + _off), "l"(_ws + _off)); \
    } \
    asm volatile("cp.async.commit_group;"); \
} while (0)

    LOAD_TILE(0);

#pragma unroll 1
    for (int i = 0; i < 12; i++) {
        if (i + 1 < 12) {
            LOAD_TILE(i + 1);
            asm volatile("cp.async.wait_group 1;");
        } else {
            asm volatile("cp.async.wait_group 0;");
        }
        __syncthreads();
        int st = i & 1;
        const uint32_t* As = reinterpret_cast<const uint32_t*>(smem + st * STG_BYTES);
        const char* Bs = smem + st * STG_BYTES + 18432;

        uint32_t ar[4][2][4];
        {
            int r0 = warp * 32 + gid;
#pragma unroll
            for (int q = 0; q < 4; q++)
#pragma unroll
                for (int mt = 0; mt < 2; mt++) {
                    int row = r0 + mt * 16;
                    ar[q][mt][0] = As[row * 36 + q * 8 + tid4];
                    ar[q][mt][1] = As[(row + 8) * 36 + q * 8 + tid4];
                    ar[q][mt][2] = As[row * 36 + q * 8 + 4 + tid4];
                    ar[q][mt][3] = As[(row + 8) * 36 + q * 8 + 4 + tid4];
                }
        }
#pragma unroll
        for (int kx = 0; kx < 3; kx++) {
            uint32_t bw[4][4][2];
#pragma unroll
            for (int s = 0; s < 4; s++)
#pragma unroll
                for (int nt = 0; nt < 4; nt++) {
                    unsigned long long v = *reinterpret_cast<const unsigned long long*>(
                        Bs + ((kx * 4 + s) * 4 + nt) * 256 + lane * 8);
                    bw[s][nt][0] = (uint32_t)v;
                    bw[s][nt][1] = (uint32_t)(v >> 32);
                }
#pragma unroll
            for (int mt = 0; mt < 2; mt++)
#pragma unroll
                for (int nt = 0; nt < 4; nt++) {
                    float* c = acc[mt][kx * 4 + nt];
                    MMA16816(c, ar[0][mt], bw[0][nt][0], bw[0][nt][1]);
                    MMA16816(c, ar[1][mt], bw[1][nt][0], bw[1][nt][1]);
                    MMA16816(c, ar[0][mt], bw[2][nt][0], bw[2][nt][1]);
                    MMA16816(c, ar[1][mt], bw[3][nt][0], bw[3][nt][1]);
                    MMA16816(c, ar[2][mt], bw[0][nt][0], bw[0][nt][1]);
                    MMA16816(c, ar[3][mt], bw[1][nt][0], bw[1][nt][1]);
                }
        }
        __syncthreads();
    }

    float* S = reinterpret_cast<float*>(smem);
#pragma unroll
    for (int mt = 0; mt < 2; mt++)
#pragma unroll
        for (int ng = 0; ng < 12; ng++) {
            int row = warp * 32 + mt * 16 + gid;
            int col = ng * 8 + tid4 * 2;
            S[row * 100 + col]           = acc[mt][ng][0];
            S[row * 100 + col + 1]       = acc[mt][ng][1];
            S[(row + 8) * 100 + col]     = acc[mt][ng][2];
            S[(row + 8) * 100 + col + 1] = acc[mt][ng][3];
        }
    __syncthreads();

    int p = tid;
    int gx = x0 + p;
    if (p >= 1 && p <= 126 && gx < WW) {
        float* hp = g_h + (size_t)b * SFC * HWC + (size_t)gy * WW + gx;
#pragma unroll
        for (int o = 0; o < 32; o++) {
            float v = S[(p - 1) * 100 + o] + S[p * 100 + 32 + o] + S[(p + 1) * 100 + 64 + o];
            hp[(size_t)o * HWC] = v;
        }
    }
}

extern "C" void kernel_launch(void* const* d_in, const int* in_sizes, int n_in,
                              void* d_out, int out_size) {
    const float* x = nullptr;
    const float* w_last = nullptr;
    const float* w_fin = nullptr;
    const float* wN[4] = {nullptr, nullptr, nullptr, nullptr};
    const float* s32[10];
    int nw = 0, ns = 0;
    const int XSZ = (int)((size_t)BB * CIN * HWC);
    for (int i = 0; i < n_in; i++) {
        int sz = in_sizes[i];
        const float* ptr = (const float*)d_in[i];
        if (sz == XSZ) x = ptr;
        else if (sz == 32 * 128 * 9) w_last = ptr;
        else if (sz == 32 * 32) w_fin = ptr;
        else if (sz == 32 * 8) { if (nw < 4) wN[nw++] = ptr; }
        else if (sz == 32) { if (ns < 10) s32[ns++] = ptr; }
    }
    const float *g1, *b1, *g2, *b2, *g3, *b3, *g4, *b4, *g_last, *b_last;
    if (in_sizes[0] == XSZ) {
        g1 = s32[0]; b1 = s32[1]; g2 = s32[2]; b2 = s32[3];
        g3 = s32[4]; b3 = s32[5]; g4 = s32[6]; b4 = s32[7];
        g_last = s32[8]; b_last = s32[9];
    } else {
        b1 = s32[0]; b2 = s32[1]; b3 = s32[2]; b4 = s32[3]; b_last = s32[4];
        g1 = s32[5]; g2 = s32[6]; g3 = s32[7]; g4 = s32[8]; g_last = s32[9];
    }
    float* out = (float*)d_out;

    cudaFuncSetAttribute(k_convmma2, cudaFuncAttributeMaxDynamicSharedMemorySize, SMEM_CONV);

    k_zero<<<1, 512>>>();
    k_norm<<<NPIX / 256, 256>>>(x);
    k_aff<<<NPIX / 256, 256>>>();
    k_mom<<<dim3(4, 100), 256>>>();
    k_bnfin128<<<1, 128>>>(wN[0], wN[1], wN[2], wN[3], g1, b1, g2, b2, g3, b3, g4, b4);
    k_expand<<<NPIX / 256, 256>>>(wN[0], wN[1], wN[2], wN[3]);
    k_wprep2<<<144, 256>>>(w_last);
    k_convmma2<<<dim3(6, HH, BB), 128, SMEM_CONV>>>();
    k_stats<<<dim3(32, 25), 256>>>(1, 32, 352);
    k_bnfin32<<<1, 32>>>(g_last, b_last);
    k_final<<<NPIX / 256, 256>>>(w_fin, out);
}

// round 16
// speedup vs baseline: 1.1377x; 1.0611x over previous
#include <cuda_runtime.h>
#include <cuda_bf16.h>
#include <cstdint>

#define BB   4
#define CIN  32
#define HH   320
#define WW   640
#define HWC  (HH*WW)
#define NPIX (BB*HWC)
#define CCAT 128
#define SFC  32

// ---------------- device scratch ----------------
__device__ float g_xn[(size_t)NPIX * CIN];                          // planar normalized x
__device__ __align__(16) float g_a[(size_t)NPIX * 32];              // planar clamped affinities [q][pix]
__device__ __align__(256) unsigned int g_fbf[(size_t)NPIX * CCAT];  // [chunk4][pix][32 u32: hi16|lo16]
__device__ float g_h[(size_t)NPIX * SFC];                           // planar pre-BN
__device__ __align__(128) unsigned int g_wm[36864];                 // mma-fragment-ordered weights
__device__ float g_stats[512];  // [di*44+t] upper-tri M, [di*44+36+k] mean sums; [352..384) h sum; [384..416) h sumsq
__device__ float g_bn[512];     // [0..128) sc feats, [128..256) sh feats, [256..288) sc h, [288..320) sh h

__device__ __forceinline__ uint32_t smem_u32(const void* p) {
    uint32_t a;
    asm("{ .reg .u64 t; cvta.to.shared.u64 t, %1; cvt.u32.u64 %0, t; }" : "=r"(a) : "l"(p));
    return a;
}
#define MMA16816(c, a, b0v, b1v) \
    asm volatile("mma.sync.aligned.m16n8k16.row.col.f32.bf16.bf16.f32 " \
                 "{%0,%1,%2,%3},{%4,%5,%6,%7},{%8,%9},{%0,%1,%2,%3};" \
                 : "+f"((c)[0]), "+f"((c)[1]), "+f"((c)[2]), "+f"((c)[3]) \
                 : "r"((a)[0]), "r"((a)[1]), "r"((a)[2]), "r"((a)[3]), "r"(b0v), "r"(b1v))

__global__ void k_zero() { g_stats[threadIdx.x] = 0.f; }

__global__ void k_norm(const float* __restrict__ x) {
    int idx = blockIdx.x * 256 + threadIdx.x;
    int b = idx / HWC, p = idx - b * HWC;
    const float* xp = x + (size_t)b * CIN * HWC + p;
    float* op = g_xn + (size_t)b * CIN * HWC + p;
    float v[CIN]; float ss = 0.f;
#pragma unroll
    for (int c = 0; c < CIN; c++) { v[c] = xp[(size_t)c * HWC]; ss += v[c] * v[c]; }
    float rn = 1.f / fmaxf(sqrtf(ss), 1e-12f);
#pragma unroll
    for (int c = 0; c < CIN; c++) op[(size_t)c * HWC] = v[c] * rn;
}

// affinity with symmetry: compute 4 FORWARD taps per dilation (k=4..7), write both
// a[di*8+k][p] and the partner a[di*8+(7-k)][p+off]. OOB entries pre-zeroed by memset.
// Forward taps (unfold order): k=4:(0,1)  k=5:(1,-1)  k=6:(1,0)  k=7:(1,1)
__global__ void k_aff() {
    int idx = blockIdx.x * 256 + threadIdx.x;
    int b = idx / HWC, p = idx - b * HWC;
    int y = p / WW, xx = p - y * WW;
    const float* xb = g_xn + (size_t)b * CIN * HWC;
    float cv[CIN];
#pragma unroll
    for (int c = 0; c < CIN; c++) cv[c] = xb[(size_t)c * HWC + p];
#pragma unroll 1
    for (int di = 0; di < 4; di++) {
        int d = 1 << di;
#pragma unroll
        for (int k = 4; k < 8; k++) {
            int iy = (k == 4) ? 0 : 1;
            int jx = (k == 4) ? 1 : (k == 5 ? -1 : (k == 6 ? 0 : 1));
            int ny = y + iy * d, nx = xx + jx * d;
            if ((unsigned)ny < HH && (unsigned)nx < WW) {
                int np = ny * WW + nx;
                float dot = 0.f;
#pragma unroll
                for (int c = 0; c < CIN; c++) dot += cv[c] * xb[(size_t)c * HWC + np];
                float av = fmaxf(dot, 0.f);
                int off = iy * d * WW + jx * d;
                g_a[(size_t)(di * 8 + k) * NPIX + idx] = av;
                g_a[(size_t)(di * 8 + (7 - k)) * NPIX + idx + off] = av;
            }
        }
    }
}

// affinity moments per branch (float4 pixels, 400 CTAs)
__global__ void __launch_bounds__(256) k_mom() {
    int di = blockIdx.x;
    int slice = blockIdx.y;
    int tid = threadIdx.x;
    int lane = tid & 31;
    float m[8];
    float M[36];
#pragma unroll
    for (int j = 0; j < 8; j++) m[j] = 0.f;
#pragma unroll
    for (int t = 0; t < 36; t++) M[t] = 0.f;
    const int NP4 = NPIX / 4;
    int e0 = slice * 2048;
    for (int e = e0 + tid; e < e0 + 2048; e += 256) {
        float4 av[8];
#pragma unroll
        for (int k = 0; k < 8; k++)
            av[k] = reinterpret_cast<const float4*>(g_a)[(size_t)(di * 8 + k) * NP4 + e];
        int t = 0;
#pragma unroll
        for (int j = 0; j < 8; j++) {
            m[j] += (av[j].x + av[j].y) + (av[j].z + av[j].w);
#pragma unroll
            for (int k = j; k < 8; k++) {
                float s = av[j].x * av[k].x;
                s = fmaf(av[j].y, av[k].y, s);
                s = fmaf(av[j].z, av[k].z, s);
                s = fmaf(av[j].w, av[k].w, s);
                M[t] += s;
                t++;
            }
        }
    }
#pragma unroll
    for (int t = 0; t < 36; t++) {
        float w = M[t];
#pragma unroll
        for (int off = 16; off > 0; off >>= 1) w += __shfl_xor_sync(0xffffffffu, w, off);
        if (lane == 0) atomicAdd(&g_stats[di * 44 + t], w);
    }
#pragma unroll
    for (int j = 0; j < 8; j++) {
        float v = m[j];
#pragma unroll
        for (int off = 16; off > 0; off >>= 1) v += __shfl_xor_sync(0xffffffffu, v, off);
        if (lane == 0) atomicAdd(&g_stats[di * 44 + 36 + j], v);
    }
}

__global__ void k_bnfin128(const float* __restrict__ w1, const float* __restrict__ w2,
                           const float* __restrict__ w3, const float* __restrict__ w4,
                           const float* __restrict__ g1, const float* __restrict__ b1,
                           const float* __restrict__ g2, const float* __restrict__ b2,
                           const float* __restrict__ g3, const float* __restrict__ b3,
                           const float* __restrict__ g4, const float* __restrict__ b4) {
    int c = threadIdx.x;
    int di = c >> 5, o = c & 31;
    const float* ws[4] = {w1, w2, w3, w4};
    const float* gs[4] = {g1, g2, g3, g4};
    const float* bs[4] = {b1, b2, b3, b4};
    float inv = 1.0f / (float)NPIX;
    const float* w = ws[di] + o * 8;
    const float* st = &g_stats[di * 44];
    float mean = 0.f;
#pragma unroll
    for (int k = 0; k < 8; k++) mean = fmaf(w[k], st[36 + k] * inv, mean);
    float ehh = 0.f;
    int t = 0;
#pragma unroll
    for (int j = 0; j < 8; j++) {
#pragma unroll
        for (int k = j; k < 8; k++) {
            float coef = (k == j) ? (w[j] * w[j]) : (2.f * w[j] * w[k]);
            ehh = fmaf(coef, st[t], ehh);
            t++;
        }
    }
    ehh *= inv;
    float var = ehh - mean * mean;
    float sc = gs[di][o] * rsqrtf(fmaxf(var, 0.f) + 1e-5f);
    g_bn[c] = sc;
    g_bn[128 + c] = bs[di][o] - mean * sc;
}

__global__ void k_stats(int which, int nch, int statoff) {
    const float* buf = which ? g_h : g_a;
    int c = blockIdx.x, slice = blockIdx.y, tid = threadIdx.x;
    const int P4 = HWC / 4;
    float s = 0.f, q = 0.f;
    int e0 = slice * 8192;
    for (int e = e0 + tid; e < e0 + 8192; e += 256) {
        int b = e / P4, p4 = e - b * P4;
        const float4* plane = reinterpret_cast<const float4*>(buf + ((size_t)b * nch + c) * HWC);
        float4 v = plane[p4];
        s += v.x + v.y + v.z + v.w;
        q += v.x * v.x + v.y * v.y + v.z * v.z + v.w * v.w;
    }
    __shared__ float ss[256], sq[256];
    ss[tid] = s; sq[tid] = q;
    __syncthreads();
    for (int off = 128; off > 0; off >>= 1) {
        if (tid < off) { ss[tid] += ss[tid + off]; sq[tid] += sq[tid + off]; }
        __syncthreads();
    }
    if (tid == 0) {
        atomicAdd(&g_stats[statoff + c], ss[0]);
        atomicAdd(&g_stats[statoff + nch + c], sq[0]);
    }
}

__global__ void k_bnfin32(const float* __restrict__ gl, const float* __restrict__ bl) {
    int o = threadIdx.x;
    float inv = 1.0f / (float)NPIX;
    float mean = g_stats[352 + o] * inv;
    float var = g_stats[384 + o] * inv - mean * mean;
    float sc = gl[o] * rsqrtf(fmaxf(var, 0.f) + 1e-5f);
    g_bn[256 + o] = sc;
    g_bn[288 + o] = bl[o] - mean * sc;
}

__global__ void __launch_bounds__(256) k_expand(const float* __restrict__ w1, const float* __restrict__ w2,
                                                const float* __restrict__ w3, const float* __restrict__ w4) {
    __shared__ float s_w[1024];
    __shared__ unsigned int s_out[256][33];
    int tid = threadIdx.x;
    {
        const float* ws[4] = {w1, w2, w3, w4};
        for (int e = tid; e < 1024; e += 256) s_w[e] = ws[e >> 8][e & 255];
    }
    __syncthreads();
    int idx = blockIdx.x * 256 + tid;
    float a[32];
#pragma unroll
    for (int q = 0; q < 32; q++) a[q] = g_a[(size_t)q * NPIX + idx];

#pragma unroll 1
    for (int di = 0; di < 4; di++) {
        float yv[32];
#pragma unroll
        for (int o = 0; o < 32; o++) {
            float s = 0.f;
            const float* wd = &s_w[di * 256 + o * 8];
#pragma unroll
            for (int k = 0; k < 8; k++) s = fmaf(a[di * 8 + k], wd[k], s);
            int ch = di * 32 + o;
            yv[o] = fmaxf(fmaf(s, g_bn[ch], g_bn[128 + ch]), 0.f);
        }
        __syncthreads();
#pragma unroll
        for (int j = 0; j < 16; j++) {
            __nv_bfloat16 h0 = __float2bfloat16_rn(yv[2 * j]);
            __nv_bfloat16 h1 = __float2bfloat16_rn(yv[2 * j + 1]);
            unsigned short l0 = __bfloat16_as_ushort(__float2bfloat16_rn(yv[2 * j] - __bfloat162float(h0)));
            unsigned short l1 = __bfloat16_as_ushort(__float2bfloat16_rn(yv[2 * j + 1] - __bfloat162float(h1)));
            s_out[tid][j] = (uint32_t)__bfloat16_as_ushort(h0) | ((uint32_t)__bfloat16_as_ushort(h1) << 16);
            s_out[tid][16 + j] = (uint32_t)l0 | ((uint32_t)l1 << 16);
        }
        __syncthreads();
        size_t base = (size_t)di * NPIX * 32 + (size_t)blockIdx.x * 256 * 32;
        for (int e = tid; e < 8192; e += 256)
            g_fbf[base + e] = s_out[e >> 5][e & 31];
    }
}

__global__ void k_final(const float* __restrict__ wf, float* __restrict__ out) {
    __shared__ float s_wf[1024];
    int tid = threadIdx.x;
#pragma unroll
    for (int it = 0; it < 4; it++) s_wf[tid + it * 256] = wf[tid + it * 256];
    __syncthreads();
    int idx = blockIdx.x * 256 + tid;
    int b = idx / HWC, p = idx - b * HWC;
    const float* hb = g_h + (size_t)b * SFC * HWC + p;
    float y[32];
#pragma unroll
    for (int c = 0; c < 32; c++) {
        float v = hb[(size_t)c * HWC];
        y[c] = fmaxf(fmaf(v, g_bn[256 + c], g_bn[288 + c]), 0.f);
    }
    float* op = out + (size_t)b * SFC * HWC + p;
#pragma unroll
    for (int o = 0; o < 32; o++) {
        float s = 0.f;
#pragma unroll
        for (int c = 0; c < 32; c++) s += y[c] * s_wf[o * 32 + c];
        op[(size_t)o * HWC] = s;
    }
}

__global__ void k_wprep2(const float* __restrict__ w_last) {
    int u = blockIdx.x * 256 + threadIdx.x;
    int tile = u / 3072;
    int ky = tile >> 2, chunk = tile & 3;
    int rem = u - tile * 3072;
    int idx = rem >> 6;
    int lr = rem & 63;
    int l = lr >> 1, r = lr & 1;
    int kx = idx >> 4;
    int s = (idx >> 2) & 3;
    int nt = idx & 3;
    int gid = l >> 2, tid4 = l & 3;
    int o = nt * 8 + gid;
    int kloc = 2 * tid4 + r * 8;
    int c0 = chunk * 32 + (s & 1) * 16 + kloc;
    int tap = ky * 3 + kx;
    float w0 = w_last[o * 1152 + c0 * 9 + tap];
    float w1 = w_last[o * 1152 + (c0 + 1) * 9 + tap];
    unsigned short q0, q1;
    if (s < 2) {
        q0 = __bfloat16_as_ushort(__float2bfloat16_rn(w0));
        q1 = __bfloat16_as_ushort(__float2bfloat16_rn(w1));
    } else {
        __nv_bfloat16 h0 = __float2bfloat16_rn(w0), h1 = __float2bfloat16_rn(w1);
        q0 = __bfloat16_as_ushort(__float2bfloat16_rn(w0 - __bfloat162float(h0)));
        q1 = __bfloat16_as_ushort(__float2bfloat16_rn(w1 - __bfloat162float(h1)));
    }
    g_wm[u] = (uint32_t)q0 | ((uint32_t)q1 << 16);
}

#define STG_BYTES 30720
#define SMEM_CONV (2 * STG_BYTES)

__global__ void __launch_bounds__(128) k_convmma2() {
    extern __shared__ __align__(16) char smem[];
    const uint32_t sbase = smem_u32(smem);
    int tid = threadIdx.x;
    int warp = tid >> 5, lane = tid & 31;
    int gid = lane >> 2, tid4 = lane & 3;
    int x0 = blockIdx.x * 126 - 1;
    int gy = blockIdx.y, b = blockIdx.z;

    float acc[2][12][4];
#pragma unroll
    for (int mt = 0; mt < 2; mt++)
#pragma unroll
        for (int n = 0; n < 12; n++)
#pragma unroll
            for (int e = 0; e < 4; e++) acc[mt][n][e] = 0.f;

#define LOAD_TILE(I) do { \
    int _ky = (I) >> 2, _ck = (I) & 3, _st = (I) & 1; \
    uint32_t _ab = sbase + _st * STG_BYTES; \
    uint32_t _bb = _ab + 18432; \
    int _yy = gy + _ky - 1; \
    int _gx = x0 + tid; \
    bool _ok = ((unsigned)_yy < HH) && ((unsigned)_gx < WW); \
    size_t _pix = (size_t)b * HWC + (size_t)(_ok ? _yy : 0) * WW + (_ok ? _gx : 0); \
    const char* _src = (const char*)g_fbf + ((size_t)_ck * NPIX + _pix) * 128; \
    uint32_t _dst = _ab + tid * 144; \
    int _sz = _ok ? 16 : 0; \
    _Pragma("unroll") \
    for (int _j = 0; _j < 8; _j++) \
        asm volatile("cp.async.cg.shared.global [%0], [%1], 16, %2;" \
                     :: "r"(_dst + _j * 16), "l"(_src + _j * 16), "r"(_sz)); \
    const char* _ws = (const char*)g_wm + (size_t)(I) * 12288; \
    _Pragma("unroll") \
    for (int _j = 0; _j < 6; _j++) { \
        int _off = (tid + _j * 128) * 16; \
        asm volatile("cp.async.cg.shared.global [%0], [%1], 16, 16;" \
                     :: "r"(_bb + _off), "l"(_ws + _off)); \
    } \
    asm volatile("cp.async.commit_group;"); \
} while (0)

    LOAD_TILE(0);

#pragma unroll 1
    for (int i = 0; i < 12; i++) {
        if (i + 1 < 12) {
            LOAD_TILE(i + 1);
            asm volatile("cp.async.wait_group 1;");
        } else {
            asm volatile("cp.async.wait_group 0;");
        }
        __syncthreads();
        int st = i & 1;
        const uint32_t* As = reinterpret_cast<const uint32_t*>(smem + st * STG_BYTES);
        const char* Bs = smem + st * STG_BYTES + 18432;

        uint32_t ar[4][2][4];
        {
            int r0 = warp * 32 + gid;
#pragma unroll
            for (int q = 0; q < 4; q++)
#pragma unroll
                for (int mt = 0; mt < 2; mt++) {
                    int row = r0 + mt * 16;
                    ar[q][mt][0] = As[row * 36 + q * 8 + tid4];
                    ar[q][mt][1] = As[(row + 8) * 36 + q * 8 + tid4];
                    ar[q][mt][2] = As[row * 36 + q * 8 + 4 + tid4];
                    ar[q][mt][3] = As[(row + 8) * 36 + q * 8 + 4 + tid4];
                }
        }
#pragma unroll
        for (int kx = 0; kx < 3; kx++) {
            uint32_t bw[4][4][2];
#pragma unroll
            for (int s = 0; s < 4; s++)
#pragma unroll
                for (int nt = 0; nt < 4; nt++) {
                    unsigned long long v = *reinterpret_cast<const unsigned long long*>(
                        Bs + ((kx * 4 + s) * 4 + nt) * 256 + lane * 8);
                    bw[s][nt][0] = (uint32_t)v;
                    bw[s][nt][1] = (uint32_t)(v >> 32);
                }
#pragma unroll
            for (int mt = 0; mt < 2; mt++)
#pragma unroll
                for (int nt = 0; nt < 4; nt++) {
                    float* c = acc[mt][kx * 4 + nt];
                    MMA16816(c, ar[0][mt], bw[0][nt][0], bw[0][nt][1]);
                    MMA16816(c, ar[1][mt], bw[1][nt][0], bw[1][nt][1]);
                    MMA16816(c, ar[0][mt], bw[2][nt][0], bw[2][nt][1]);
                    MMA16816(c, ar[1][mt], bw[3][nt][0], bw[3][nt][1]);
                    MMA16816(c, ar[2][mt], bw[0][nt][0], bw[0][nt][1]);
                    MMA16816(c, ar[3][mt], bw[1][nt][0], bw[1][nt][1]);
                }
        }
        __syncthreads();
    }

    float* S = reinterpret_cast<float*>(smem);
#pragma unroll
    for (int mt = 0; mt < 2; mt++)
#pragma unroll
        for (int ng = 0; ng < 12; ng++) {
            int row = warp * 32 + mt * 16 + gid;
            int col = ng * 8 + tid4 * 2;
            S[row * 100 + col]           = acc[mt][ng][0];
            S[row * 100 + col + 1]       = acc[mt][ng][1];
            S[(row + 8) * 100 + col]     = acc[mt][ng][2];
            S[(row + 8) * 100 + col + 1] = acc[mt][ng][3];
        }
    __syncthreads();

    int p = tid;
    int gx = x0 + p;
    if (p >= 1 && p <= 126 && gx < WW) {
        float* hp = g_h + (size_t)b * SFC * HWC + (size_t)gy * WW + gx;
#pragma unroll
        for (int o = 0; o < 32; o++) {
            float v = S[(p - 1) * 100 + o] + S[p * 100 + 32 + o] + S[(p + 1) * 100 + 64 + o];
            hp[(size_t)o * HWC] = v;
        }
    }
}

extern "C" void kernel_launch(void* const* d_in, const int* in_sizes, int n_in,
                              void* d_out, int out_size) {
    const float* x = nullptr;
    const float* w_last = nullptr;
    const float* w_fin = nullptr;
    const float* wN[4] = {nullptr, nullptr, nullptr, nullptr};
    const float* s32[10];
    int nw = 0, ns = 0;
    const int XSZ = (int)((size_t)BB * CIN * HWC);
    for (int i = 0; i < n_in; i++) {
        int sz = in_sizes[i];
        const float* ptr = (const float*)d_in[i];
        if (sz == XSZ) x = ptr;
        else if (sz == 32 * 128 * 9) w_last = ptr;
        else if (sz == 32 * 32) w_fin = ptr;
        else if (sz == 32 * 8) { if (nw < 4) wN[nw++] = ptr; }
        else if (sz == 32) { if (ns < 10) s32[ns++] = ptr; }
    }
    const float *g1, *b1, *g2, *b2, *g3, *b3, *g4, *b4, *g_last, *b_last;
    if (in_sizes[0] == XSZ) {
        g1 = s32[0]; b1 = s32[1]; g2 = s32[2]; b2 = s32[3];
        g3 = s32[4]; b3 = s32[5]; g4 = s32[6]; b4 = s32[7];
        g_last = s32[8]; b_last = s32[9];
    } else {
        b1 = s32[0]; b2 = s32[1]; b3 = s32[2]; b4 = s32[3]; b_last = s32[4];
        g1 = s32[5]; g2 = s32[6]; g3 = s32[7]; g4 = s32[8]; g_last = s32[9];
    }
    float* out = (float*)d_out;

    cudaFuncSetAttribute(k_convmma2, cudaFuncAttributeMaxDynamicSharedMemorySize, SMEM_CONV);

    // zero g_a so OOB-adjacent affinity entries stay 0 (symmetric k_aff skips them)
    void* a_ptr = nullptr;
    cudaGetSymbolAddress(&a_ptr, g_a);
    cudaMemsetAsync(a_ptr, 0, sizeof(float) * (size_t)NPIX * 32, 0);

    k_zero<<<1, 512>>>();
    k_norm<<<NPIX / 256, 256>>>(x);
    k_aff<<<NPIX / 256, 256>>>();
    k_mom<<<dim3(4, 100), 256>>>();
    k_bnfin128<<<1, 128>>>(wN[0], wN[1], wN[2], wN[3], g1, b1, g2, b2, g3, b3, g4, b4);
    k_expand<<<NPIX / 256, 256>>>(wN[0], wN[1], wN[2], wN[3]);
    k_wprep2<<<144, 256>>>(w_last);
    k_convmma2<<<dim3(6, HH, BB), 128, SMEM_CONV>>>();
    k_stats<<<dim3(32, 25), 256>>>(1, 32, 352);
    k_bnfin32<<<1, 32>>>(g_last, b_last);
    k_final<<<NPIX / 256, 256>>>(w_fin, out);
}